// round 1
// baseline (speedup 1.0000x reference)
#include <cuda_runtime.h>
#include <cstdint>
#include <math.h>

// Problem constants (fixed by the dataset)
#define NROWS 200000
#define CCH   256
#define BGR   4
#define GRP   32
#define KTAP  27
#define CEMB  1024
#define TM    64
#define KI    64
#define EPSV  1e-5f

// -------- scratch (static __device__ — no runtime allocation) --------
__device__ float g_xa[(size_t)NROWS * CCH];       // 204.8 MB activation scratch
__device__ float g_sum[BGR * CCH];
__device__ float g_sq[BGR * CCH];
__device__ float g_mean[BGR * GRP];
__device__ float g_rstd[BGR * GRP];
__device__ int   g_cnt[BGR];
__device__ float g_ss[BGR * 2 * CCH];             // emb MLP out: scale|shift per grid

// ---------------------------------------------------------------------
__device__ __forceinline__ float silu_f(float v) {
    return v / (1.0f + expf(-v));
}

__device__ __forceinline__ void cp_async16(void* dst, const void* src) {
    unsigned sdst = (unsigned)__cvta_generic_to_shared(dst);
    asm volatile("cp.async.cg.shared.global [%0], [%1], 16;" :: "r"(sdst), "l"(src));
}

// -------- reset accumulators (must run every launch: graph replay) -----
__global__ void reset_kernel(int zero_cnt) {
    int t = blockIdx.x * blockDim.x + threadIdx.x;
    if (t < BGR * CCH) { g_sum[t] = 0.0f; g_sq[t] = 0.0f; }
    if (zero_cnt && t < BGR) g_cnt[t] = 0;
}

// -------- per-grid voxel counts --------
__global__ void count_kernel(const int* __restrict__ jidx, int n) {
    int c0 = 0, c1 = 0, c2 = 0, c3 = 0;
    for (int i = blockIdx.x * blockDim.x + threadIdx.x; i < n;
         i += gridDim.x * blockDim.x) {
        int b = jidx[i];
        c0 += (b == 0); c1 += (b == 1); c2 += (b == 2); c3 += (b == 3);
    }
    if (c0) atomicAdd(&g_cnt[0], c0);
    if (c1) atomicAdd(&g_cnt[1], c1);
    if (c2) atomicAdd(&g_cnt[2], c2);
    if (c3) atomicAdd(&g_cnt[3], c3);
}

// -------- per-(grid, channel) sum / sumsq --------
__global__ void stats_kernel(const float* __restrict__ x,
                             const int* __restrict__ jidx, int nrows) {
    const int t = threadIdx.x;                // channel, blockDim = 256
    int r0 = blockIdx.x * 512;
    int r1 = r0 + 512; if (r1 > nrows) r1 = nrows;
    float s = 0.0f, sq = 0.0f; int cur = -1;
    for (int r = r0; r < r1; ++r) {
        int b = jidx[r];
        if (b != cur) {
            if (cur >= 0) {
                atomicAdd(&g_sum[cur * CCH + t], s);
                atomicAdd(&g_sq[cur * CCH + t], sq);
            }
            cur = b; s = 0.0f; sq = 0.0f;
        }
        float v = x[(size_t)r * CCH + t];
        s += v; sq += v * v;
    }
    if (cur >= 0) {
        atomicAdd(&g_sum[cur * CCH + t], s);
        atomicAdd(&g_sq[cur * CCH + t], sq);
    }
}

// -------- fold channel sums into per-(grid, group) mean / rstd --------
__global__ void finalize_kernel() {
    int t = threadIdx.x;
    if (t < BGR * GRP) {
        int b = t / GRP, g = t % GRP;
        float s = 0.0f, sq = 0.0f;
        #pragma unroll
        for (int j = 0; j < 8; ++j) {
            s  += g_sum[b * CCH + g * 8 + j];
            sq += g_sq [b * CCH + g * 8 + j];
        }
        float denom = (float)g_cnt[b] * 8.0f;
        float mean = s / denom;
        float var  = sq / denom - mean * mean;
        g_mean[t] = mean;
        g_rstd[t] = rsqrtf(var + EPSV);
    }
}

// -------- GN1 + SiLU --------
__global__ void norm1_kernel(const float* __restrict__ x,
                             const int* __restrict__ jidx,
                             const float* __restrict__ w,
                             const float* __restrict__ bb,
                             float* __restrict__ out) {
    size_t i4 = (size_t)blockIdx.x * blockDim.x + threadIdx.x;
    if (i4 >= (size_t)NROWS * (CCH / 4)) return;
    int n = (int)(i4 >> 6);
    int c = ((int)i4 & 63) * 4;
    int b = jidx[n];
    int g = c >> 3;
    float mean = g_mean[b * GRP + g];
    float rstd = g_rstd[b * GRP + g];
    float4 xv = *(const float4*)(x + i4 * 4);
    float4 wv = *(const float4*)(w + c);
    float4 bv = *(const float4*)(bb + c);
    float4 o;
    o.x = silu_f((xv.x - mean) * rstd * wv.x + bv.x);
    o.y = silu_f((xv.y - mean) * rstd * wv.y + bv.y);
    o.z = silu_f((xv.z - mean) * rstd * wv.z + bv.z);
    o.w = silu_f((xv.w - mean) * rstd * wv.w + bv.w);
    *(float4*)(out + i4 * 4) = o;
}

// -------- embedding MLP: g_ss[b][0:256]=scale, [256:512]=shift --------
__global__ void emb_kernel(const float* __restrict__ emb,
                           const float* __restrict__ ew,
                           const float* __restrict__ eb) {
    __shared__ float se[CEMB];
    int b = blockIdx.x;
    int t = threadIdx.x;                       // blockDim = 512
    for (int i = t; i < CEMB; i += 512) {
        float v = emb[b * CEMB + i];
        se[i] = silu_f(v);
    }
    __syncthreads();
    float acc = eb[t];
    for (int i = 0; i < CEMB; ++i)
        acc += se[i] * ew[i * (2 * CCH) + t];
    g_ss[b * (2 * CCH) + t] = acc;
}

// -------- GN2 + FiLM + SiLU --------
__global__ void norm2_kernel(const float* __restrict__ x,
                             const int* __restrict__ jidx,
                             const float* __restrict__ w,
                             const float* __restrict__ bb,
                             float* __restrict__ out) {
    size_t i4 = (size_t)blockIdx.x * blockDim.x + threadIdx.x;
    if (i4 >= (size_t)NROWS * (CCH / 4)) return;
    int n = (int)(i4 >> 6);
    int c = ((int)i4 & 63) * 4;
    int b = jidx[n];
    int g = c >> 3;
    float mean = g_mean[b * GRP + g];
    float rstd = g_rstd[b * GRP + g];
    float4 xv = *(const float4*)(x + i4 * 4);
    float4 wv = *(const float4*)(w + c);
    float4 bv = *(const float4*)(bb + c);
    float4 sc = *(const float4*)(g_ss + b * (2 * CCH) + c);
    float4 sh = *(const float4*)(g_ss + b * (2 * CCH) + CCH + c);
    float4 o;
    float t0;
    t0 = (xv.x - mean) * rstd * wv.x + bv.x; o.x = silu_f(t0 * (1.0f + sc.x) + sh.x);
    t0 = (xv.y - mean) * rstd * wv.y + bv.y; o.y = silu_f(t0 * (1.0f + sc.y) + sh.y);
    t0 = (xv.z - mean) * rstd * wv.z + bv.z; o.z = silu_f(t0 * (1.0f + sc.z) + sh.z);
    t0 = (xv.w - mean) * rstd * wv.w + bv.w; o.w = silu_f(t0 * (1.0f + sc.w) + sh.w);
    *(float4*)(out + i4 * 4) = o;
}

// -------- 27-tap gather sparse conv: out = sum_k gather(x,nbr_k) @ W[k] + bias (+resid)
// CTA: 64 rows x 256 cols. X tile gathered to smem; W streamed in 64-row
// K-chunks, double-buffered via cp.async. Inner math uses packed fma.rn.f32x2
// (2x fp32 rate on Blackwell; only reachable from PTX).
__global__ void __launch_bounds__(256, 1) conv_kernel(
    const float* __restrict__ x, const int* __restrict__ nbr,
    const float* __restrict__ W, const float* __restrict__ bias,
    const float* __restrict__ resid, float* __restrict__ out)
{
    extern __shared__ float smem[];
    float* Xs  = smem;                    // TM*CCH floats (64 KB)
    float* Wsm = smem + TM * CCH;         // 2 * KI*CCH floats (2 x 64 KB)
    __shared__ int sidx[TM];

    const int tid  = threadIdx.x;
    const int row0 = blockIdx.x * TM;
    const int tr   = tid >> 5;            // 0..7  (row phase)
    const int tc   = tid & 31;            // 0..31 (col phase)

    unsigned long long acc[4][8];         // 4 row-pairs x 8 cols, packed f32x2
#pragma unroll
    for (int p = 0; p < 4; ++p)
#pragma unroll
        for (int cc = 0; cc < 8; ++cc) acc[p][cc] = 0ULL;

    for (int k = 0; k < KTAP; ++k) {
        const float* Wk = W + (size_t)k * CCH * CCH;

        // prefetch W chunk 0 -> buffer 0 (buf0's last reader was prev k's
        // chunk-2 compute, already behind a __syncthreads)
        {
            const float* src = Wk;
            float* dst = Wsm;
#pragma unroll
            for (int it = 0; it < 16; ++it) {
                int lin = tid + it * 256;
                cp_async16(dst + lin * 4, src + lin * 4);
            }
            asm volatile("cp.async.commit_group;");
        }
        if (tid < TM) sidx[tid] = nbr[(size_t)(row0 + tid) * KTAP + k];
        __syncthreads();

        // gather 64 neighbor rows into Xs (zeros for missing)
#pragma unroll
        for (int it = 0; it < 16; ++it) {
            int lin = tid + it * 256;     // 0..4095
            int r   = lin >> 6;
            int c4  = lin & 63;
            int idx = sidx[r];
            float4 v = make_float4(0.f, 0.f, 0.f, 0.f);
            if (idx >= 0) v = *(const float4*)(x + (size_t)idx * CCH + c4 * 4);
            *(float4*)(Xs + r * CCH + c4 * 4) = v;
        }

#pragma unroll
        for (int ci = 0; ci < 4; ++ci) {
            if (ci < 3) {
                const float* src = Wk + (ci + 1) * KI * CCH;
                float* dst = Wsm + ((ci + 1) & 1) * KI * CCH;
#pragma unroll
                for (int it = 0; it < 16; ++it) {
                    int lin = tid + it * 256;
                    cp_async16(dst + lin * 4, src + lin * 4);
                }
                asm volatile("cp.async.commit_group;");
                asm volatile("cp.async.wait_group 1;");
            } else {
                asm volatile("cp.async.wait_group 0;");
            }
            __syncthreads();

            const float* Wb = Wsm + (ci & 1) * KI * CCH;
            const int ib = ci * KI;
#pragma unroll 4
            for (int i = 0; i < KI; ++i) {
                float a[8];
#pragma unroll
                for (int rr = 0; rr < 8; ++rr)
                    a[rr] = Xs[(tr + rr * 8) * CCH + ib + i];   // warp broadcast
                unsigned long long ap[4];
#pragma unroll
                for (int p = 0; p < 4; ++p) {
                    unsigned lo = __float_as_uint(a[2 * p]);
                    unsigned hi = __float_as_uint(a[2 * p + 1]);
                    asm("mov.b64 %0, {%1, %2};" : "=l"(ap[p]) : "r"(lo), "r"(hi));
                }
#pragma unroll
                for (int cc = 0; cc < 8; ++cc) {
                    float bvf = Wb[i * CCH + tc + cc * 32];     // conflict-free
                    unsigned bu = __float_as_uint(bvf);
                    unsigned long long bp;
                    asm("mov.b64 %0, {%1, %2};" : "=l"(bp) : "r"(bu), "r"(bu));
#pragma unroll
                    for (int p = 0; p < 4; ++p)
                        asm("fma.rn.f32x2 %0, %1, %2, %0;"
                            : "+l"(acc[p][cc]) : "l"(ap[p]), "l"(bp));
                }
            }
            __syncthreads();
        }
    }

    // epilogue: bias (+ residual), store
#pragma unroll
    for (int p = 0; p < 4; ++p)
#pragma unroll
        for (int cc = 0; cc < 8; ++cc) {
            unsigned lo_u, hi_u;
            asm("mov.b64 {%0, %1}, %2;" : "=r"(lo_u), "=r"(hi_u) : "l"(acc[p][cc]));
            float lo = __uint_as_float(lo_u);
            float hi = __uint_as_float(hi_u);
            int c  = tc + cc * 32;
            int r0 = row0 + tr + (2 * p) * 8;
            int r1 = row0 + tr + (2 * p + 1) * 8;
            float bv = bias[c];
            float v0 = lo + bv, v1 = hi + bv;
            if (resid) {
                v0 += resid[(size_t)r0 * CCH + c];
                v1 += resid[(size_t)r1 * CCH + c];
            }
            out[(size_t)r0 * CCH + c] = v0;
            out[(size_t)r1 * CCH + c] = v1;
        }
}

// ---------------------------------------------------------------------
extern "C" void kernel_launch(void* const* d_in, const int* in_sizes, int n_in,
                              void* d_out, int out_size)
{
    const float* feats = (const float*)d_in[0];
    const float* emb   = (const float*)d_in[1];
    const int*   jidx  = (const int*)  d_in[2];
    const int*   nbr   = (const int*)  d_in[3];
    const float* gn1w  = (const float*)d_in[4];
    const float* gn1b  = (const float*)d_in[5];
    const float* w1    = (const float*)d_in[6];
    const float* b1    = (const float*)d_in[7];
    const float* embw  = (const float*)d_in[8];
    const float* embb  = (const float*)d_in[9];
    const float* gn2w  = (const float*)d_in[10];
    const float* gn2b  = (const float*)d_in[11];
    const float* w2    = (const float*)d_in[12];
    const float* b2    = (const float*)d_in[13];
    float* out = (float*)d_out;

    float* xa = nullptr;
    cudaGetSymbolAddress((void**)&xa, g_xa);

    const int SMEM_CONV = (TM * CCH + 2 * KI * CCH) * (int)sizeof(float); // 192 KB
    cudaFuncSetAttribute(conv_kernel,
                         cudaFuncAttributeMaxDynamicSharedMemorySize, SMEM_CONV);

    const int nblk_norm  = (NROWS * (CCH / 4) + 255) / 256;   // 50000
    const int nblk_stats = (NROWS + 511) / 512;               // 391
    const int nblk_conv  = NROWS / TM;                        // 3125

    // --- GN1 ---
    reset_kernel<<<4, 256>>>(1);
    count_kernel<<<64, 256>>>(jidx, NROWS);
    stats_kernel<<<nblk_stats, 256>>>(feats, jidx, NROWS);
    finalize_kernel<<<1, 128>>>();
    norm1_kernel<<<nblk_norm, 256>>>(feats, jidx, gn1w, gn1b, xa);

    // --- emb MLP (independent) ---
    emb_kernel<<<BGR, 512>>>(emb, embw, embb);

    // --- conv1: h -> d_out (staging) ---
    conv_kernel<<<nblk_conv, 256, SMEM_CONV>>>(xa, nbr, w1, b1, nullptr, out);

    // --- GN2 + FiLM + SiLU ---
    reset_kernel<<<4, 256>>>(0);
    stats_kernel<<<nblk_stats, 256>>>(out, jidx, NROWS);
    finalize_kernel<<<1, 128>>>();
    norm2_kernel<<<nblk_norm, 256>>>(out, jidx, gn2w, gn2b, xa);

    // --- conv2 + residual -> d_out ---
    conv_kernel<<<nblk_conv, 256, SMEM_CONV>>>(xa, nbr, w2, b2, feats, out);
}

// round 3
// speedup vs baseline: 5.5736x; 5.5736x over previous
#include <cuda_runtime.h>
#include <cuda_bf16.h>
#include <cstdint>
#include <math.h>

// Problem constants (fixed by the dataset)
#define NROWS 200000
#define CCH   256
#define BGR   4
#define GRP   32
#define KTAP  27
#define CEMB  1024
#define EPSV  1e-5f

#define TILE_M    128
#define CHUNKS    8                    // 32-cin chunks per tap
#define NITER     (KTAP * CHUNKS)      // 216
#define NBLK_CONV ((NROWS + TILE_M - 1) / TILE_M)   // 1563

// packed row: 8 chunks x [32 hi bf16 (64B) | 32 lo bf16 (64B)] = 1024 B/row
#define ROWB   1024
#define ASTAGE 16384                   // 128 rows * 128B
#define BSTAGE 32768                   // 256 couts * 128B
#define STAGE  (ASTAGE + BSTAGE)       // 48KB per stage

// -------- scratch (static __device__ — no runtime allocation) --------
__device__ unsigned char g_xp[(size_t)NROWS * ROWB];        // 204.8 MB packed acts
__device__ unsigned char g_w1p[(size_t)KTAP * CCH * 1024];  // 6.9 MB packed weights
__device__ unsigned char g_w2p[(size_t)KTAP * CCH * 1024];
__device__ float g_sum[BGR * CCH];
__device__ float g_sq[BGR * CCH];
__device__ float g_mean[BGR * GRP];
__device__ float g_rstd[BGR * GRP];
__device__ int   g_cnt[BGR];
__device__ float g_ss[BGR * 2 * CCH];

// ---------------------------------------------------------------------
__device__ __forceinline__ float silu_f(float v) { return v / (1.0f + expf(-v)); }

__device__ __forceinline__ uint32_t s2u(const void* p) {
    return (uint32_t)__cvta_generic_to_shared(p);
}
__device__ __forceinline__ void cp16(uint32_t dst, const void* src) {
    asm volatile("cp.async.cg.shared.global [%0], [%1], 16;" :: "r"(dst), "l"(src));
}
__device__ __forceinline__ void sts16_zero(uint32_t dst) {
    asm volatile("st.shared.v4.b32 [%0], {%1,%1,%1,%1};" :: "r"(dst), "r"(0u) : "memory");
}
__device__ __forceinline__ void ldsm4(uint32_t* r, uint32_t a) {
    asm volatile("ldmatrix.sync.aligned.m8n8.x4.shared.b16 {%0,%1,%2,%3}, [%4];"
                 : "=r"(r[0]), "=r"(r[1]), "=r"(r[2]), "=r"(r[3]) : "r"(a));
}
__device__ __forceinline__ void mma_bf16(float* d, const uint32_t* a,
                                         uint32_t b0, uint32_t b1) {
    asm volatile(
        "mma.sync.aligned.m16n8k16.row.col.f32.bf16.bf16.f32 "
        "{%0,%1,%2,%3}, {%4,%5,%6,%7}, {%8,%9}, {%0,%1,%2,%3};"
        : "+f"(d[0]), "+f"(d[1]), "+f"(d[2]), "+f"(d[3])
        : "r"(a[0]), "r"(a[1]), "r"(a[2]), "r"(a[3]), "r"(b0), "r"(b1));
}

__device__ __forceinline__ void split_bf16(float v, __nv_bfloat16& h, __nv_bfloat16& l) {
    h = __float2bfloat16(v);
    l = __float2bfloat16(v - __bfloat162float(h));
}
__device__ __forceinline__ uint32_t pack2(__nv_bfloat16 a, __nv_bfloat16 b) {
    __nv_bfloat162 p = __halves2bfloat162(a, b);
    return *reinterpret_cast<uint32_t*>(&p);
}

// -------- reset accumulators (graph replay safe) --------
__global__ void reset_kernel(int zero_cnt) {
    int t = blockIdx.x * blockDim.x + threadIdx.x;
    if (t < BGR * CCH) { g_sum[t] = 0.0f; g_sq[t] = 0.0f; }
    if (zero_cnt && t < BGR) g_cnt[t] = 0;
}

__global__ void count_kernel(const int* __restrict__ jidx, int n) {
    int c0 = 0, c1 = 0, c2 = 0, c3 = 0;
    for (int i = blockIdx.x * blockDim.x + threadIdx.x; i < n;
         i += gridDim.x * blockDim.x) {
        int b = jidx[i];
        c0 += (b == 0); c1 += (b == 1); c2 += (b == 2); c3 += (b == 3);
    }
    if (c0) atomicAdd(&g_cnt[0], c0);
    if (c1) atomicAdd(&g_cnt[1], c1);
    if (c2) atomicAdd(&g_cnt[2], c2);
    if (c3) atomicAdd(&g_cnt[3], c3);
}

__global__ void stats_kernel(const float* __restrict__ x,
                             const int* __restrict__ jidx, int nrows) {
    const int t = threadIdx.x;                 // channel, blockDim = 256
    int r0 = blockIdx.x * 512;
    int r1 = r0 + 512; if (r1 > nrows) r1 = nrows;
    float s = 0.0f, sq = 0.0f; int cur = -1;
    for (int r = r0; r < r1; ++r) {
        int b = jidx[r];
        if (b != cur) {
            if (cur >= 0) {
                atomicAdd(&g_sum[cur * CCH + t], s);
                atomicAdd(&g_sq[cur * CCH + t], sq);
            }
            cur = b; s = 0.0f; sq = 0.0f;
        }
        float v = x[(size_t)r * CCH + t];
        s += v; sq += v * v;
    }
    if (cur >= 0) {
        atomicAdd(&g_sum[cur * CCH + t], s);
        atomicAdd(&g_sq[cur * CCH + t], sq);
    }
}

__global__ void finalize_kernel() {
    int t = threadIdx.x;
    if (t < BGR * GRP) {
        int b = t / GRP, g = t % GRP;
        float s = 0.0f, sq = 0.0f;
        #pragma unroll
        for (int j = 0; j < 8; ++j) {
            s  += g_sum[b * CCH + g * 8 + j];
            sq += g_sq [b * CCH + g * 8 + j];
        }
        float denom = (float)g_cnt[b] * 8.0f;
        float mean = s / denom;
        float var  = sq / denom - mean * mean;
        g_mean[t] = mean;
        g_rstd[t] = rsqrtf(var + EPSV);
    }
}

// -------- GN + SiLU -> packed bf16 hi/lo rows (film=0: GN1; film=1: GN2+FiLM) --
__global__ void norm_pack_kernel(const float* __restrict__ x,
                                 const int* __restrict__ jidx,
                                 const float* __restrict__ w,
                                 const float* __restrict__ bb,
                                 unsigned char* __restrict__ xp, int film) {
    size_t i4 = (size_t)blockIdx.x * blockDim.x + threadIdx.x;
    if (i4 >= (size_t)NROWS * (CCH / 4)) return;
    int n = (int)(i4 >> 6);
    int c = ((int)i4 & 63) * 4;
    int b = jidx[n];
    int g = c >> 3;
    float mean = g_mean[b * GRP + g];
    float rstd = g_rstd[b * GRP + g];
    float4 xv = *(const float4*)(x + i4 * 4);
    float4 wv = *(const float4*)(w + c);
    float4 bv = *(const float4*)(bb + c);
    float o[4];
    o[0] = (xv.x - mean) * rstd * wv.x + bv.x;
    o[1] = (xv.y - mean) * rstd * wv.y + bv.y;
    o[2] = (xv.z - mean) * rstd * wv.z + bv.z;
    o[3] = (xv.w - mean) * rstd * wv.w + bv.w;
    if (film) {
        float4 sc = *(const float4*)(g_ss + b * (2 * CCH) + c);
        float4 sh = *(const float4*)(g_ss + b * (2 * CCH) + CCH + c);
        o[0] = o[0] * (1.0f + sc.x) + sh.x;
        o[1] = o[1] * (1.0f + sc.y) + sh.y;
        o[2] = o[2] * (1.0f + sc.z) + sh.z;
        o[3] = o[3] * (1.0f + sc.w) + sh.w;
    }
    __nv_bfloat16 h[4], l[4];
    #pragma unroll
    for (int j = 0; j < 4; ++j) {
        float s = silu_f(o[j]);
        split_bf16(s, h[j], l[j]);
    }
    size_t base = (size_t)n * ROWB + (size_t)(c >> 5) * 128 + (size_t)(c & 31) * 2;
    uint2 hv = make_uint2(pack2(h[0], h[1]), pack2(h[2], h[3]));
    uint2 lv = make_uint2(pack2(l[0], l[1]), pack2(l[2], l[3]));
    *(uint2*)(xp + base)      = hv;
    *(uint2*)(xp + base + 64) = lv;
}

// -------- pack W[k][cin][cout] -> wp[(k*256+cout)*8 + cin/32][32hi|32lo] ------
__global__ void wpack_kernel(const float* __restrict__ W,
                             unsigned char* __restrict__ wp) {
    int bid = blockIdx.x;               // 0 .. 27*256-1
    int k = bid >> 8, cout = bid & 255;
    int cin = threadIdx.x;              // 0..255
    float v = W[((size_t)(k * CCH + cin)) * CCH + cout];
    __nv_bfloat16 h, l;
    split_bf16(v, h, l);
    size_t base = ((size_t)(k * CCH + cout) * 8 + (cin >> 5)) * 128 + (size_t)(cin & 31) * 2;
    *(__nv_bfloat16*)(wp + base)      = h;
    *(__nv_bfloat16*)(wp + base + 64) = l;
}

// -------- embedding MLP --------
__global__ void emb_kernel(const float* __restrict__ emb,
                           const float* __restrict__ ew,
                           const float* __restrict__ eb) {
    __shared__ float se[CEMB];
    int b = blockIdx.x;
    int t = threadIdx.x;                // blockDim = 512
    for (int i = t; i < CEMB; i += 512) se[i] = silu_f(emb[b * CEMB + i]);
    __syncthreads();
    float acc = eb[t];
    for (int i = 0; i < CEMB; ++i)
        acc += se[i] * ew[i * (2 * CCH) + t];
    g_ss[b * (2 * CCH) + t] = acc;
}

// ================= HMMA sparse-conv GEMM =================
// CTA: 512 thr, tile 128 rows x 256 cout. Warp grid 4m x 4n, warp tile 32x64.
// fp32 emulated as Ah*Bh + Ah*Bl + Al*Bh on bf16 mma.sync (3 passes).
__global__ void __launch_bounds__(512, 1) convmma_kernel(
    const unsigned char* __restrict__ xp, const int* __restrict__ nbr,
    const unsigned char* __restrict__ wp, const float* __restrict__ bias,
    const float* __restrict__ resid, float* __restrict__ out, int nrows)
{
    extern __shared__ unsigned char dsm[];
    const int tid  = threadIdx.x;
    const int lane = tid & 31;
    const int wid  = tid >> 5;
    const int wm   = wid & 3;            // warp m-tile (32 rows each)
    const int wn   = wid >> 2;           // warp n-tile (64 couts each)
    const int row0 = blockIdx.x * TILE_M;

    uint32_t sb = (s2u(dsm) + 1023u) & ~1023u;   // 1KB-aligned

    // ldmatrix lane decomposition
    const int l7 = lane & 7;
    const int lq = (lane >> 3) & 1;
    const int lh = (lane >> 4) & 1;

    // gather mapping: A rows (thread t -> row t>>2, 2 segs), B couts (t>>1, 4 segs)
    const int grow  = tid >> 2;
    const bool gok  = (row0 + grow) < nrows;
    const int aseg0 = (tid & 3) * 2;
    const int bco   = tid >> 1;
    const int bseg0 = (tid & 1) * 4;

    float acc[2][8][4];
#pragma unroll
    for (int mt = 0; mt < 2; ++mt)
#pragma unroll
        for (int nt = 0; nt < 8; ++nt)
#pragma unroll
            for (int q = 0; q < 4; ++q) acc[mt][nt][q] = 0.0f;

    int gidx = -1;
    auto load_chunk = [&](int j) {
        const int kk = j >> 3, cc = j & 7, buf = j & 1;
        if (cc == 0) gidx = gok ? nbr[(size_t)(row0 + grow) * KTAP + kk] : -1;
        const uint32_t ab = sb + buf * STAGE + (uint32_t)grow * 128u;
        if (gidx >= 0) {
            const unsigned char* src = xp + (size_t)gidx * ROWB + (size_t)cc * 128;
#pragma unroll
            for (int u = 0; u < 2; ++u) {
                int seg = aseg0 + u;
                cp16(ab + (uint32_t)((seg ^ (grow & 7)) * 16), src + seg * 16);
            }
        } else {
#pragma unroll
            for (int u = 0; u < 2; ++u) {
                int seg = aseg0 + u;
                sts16_zero(ab + (uint32_t)((seg ^ (grow & 7)) * 16));
            }
        }
        const unsigned char* bsrc = wp + ((size_t)(kk * CCH + bco) * 8 + cc) * 128;
        const uint32_t bb = sb + buf * STAGE + ASTAGE + (uint32_t)bco * 128u;
#pragma unroll
        for (int u = 0; u < 4; ++u) {
            int seg = bseg0 + u;
            cp16(bb + (uint32_t)((seg ^ (bco & 7)) * 16), bsrc + seg * 16);
        }
        asm volatile("cp.async.commit_group;");
    };

    load_chunk(0);

    for (int it = 0; it < NITER; ++it) {
        if (it + 1 < NITER) {
            load_chunk(it + 1);
            asm volatile("cp.async.wait_group 1;");
        } else {
            asm volatile("cp.async.wait_group 0;");
        }
        __syncthreads();

        const int buf = it & 1;
        const uint32_t ab = sb + buf * STAGE;
        const uint32_t bb = ab + ASTAGE;

#pragma unroll
        for (int ks = 0; ks < 2; ++ks) {
            // A fragments (hi and lo) for both m-tiles
            uint32_t ah[2][4], al[2][4];
#pragma unroll
            for (int mt = 0; mt < 2; ++mt) {
                const int m_r  = wm * 32 + mt * 16 + l7 + lq * 8;
                const int sg_h = ks * 2 + lh;
                const uint32_t rbase = ab + (uint32_t)m_r * 128u;
                ldsm4(ah[mt], rbase + (uint32_t)(((sg_h    ) ^ l7) * 16));
                ldsm4(al[mt], rbase + (uint32_t)(((sg_h + 4) ^ l7) * 16));
            }
#pragma unroll
            for (int p = 0; p < 4; ++p) {         // pairs of n-tiles
                const int n_r  = wn * 64 + p * 16 + lh * 8 + l7;
                const int sg_h = ks * 2 + lq;
                const uint32_t rbase = bb + (uint32_t)n_r * 128u;
                uint32_t bh[4], bl[4];
                ldsm4(bh, rbase + (uint32_t)(((sg_h    ) ^ l7) * 16));
                ldsm4(bl, rbase + (uint32_t)(((sg_h + 4) ^ l7) * 16));
#pragma unroll
                for (int mt = 0; mt < 2; ++mt)
#pragma unroll
                    for (int q = 0; q < 2; ++q) {
                        float* d = acc[mt][p * 2 + q];
                        mma_bf16(d, ah[mt], bh[2 * q], bh[2 * q + 1]);  // Ah*Bh
                        mma_bf16(d, ah[mt], bl[2 * q], bl[2 * q + 1]);  // Ah*Bl
                        mma_bf16(d, al[mt], bh[2 * q], bh[2 * q + 1]);  // Al*Bh
                    }
            }
        }
        __syncthreads();
    }

    // ---- epilogue ----
    const int tq = lane >> 2;             // 0..7
    const int tr = lane & 3;              // 0..3
#pragma unroll
    for (int mt = 0; mt < 2; ++mt) {
        const int ra = row0 + wm * 32 + mt * 16 + tq;
        const int rb2 = ra + 8;
#pragma unroll
        for (int nt = 0; nt < 8; ++nt) {
            const int c = wn * 64 + nt * 8 + tr * 2;
            const float b0 = bias[c], b1 = bias[c + 1];
            if (ra < nrows) {
                float v0 = acc[mt][nt][0] + b0;
                float v1 = acc[mt][nt][1] + b1;
                if (resid) {
                    const float2 rv = *(const float2*)(resid + (size_t)ra * CCH + c);
                    v0 += rv.x; v1 += rv.y;
                }
                *(float2*)(out + (size_t)ra * CCH + c) = make_float2(v0, v1);
            }
            if (rb2 < nrows) {
                float v0 = acc[mt][nt][2] + b0;
                float v1 = acc[mt][nt][3] + b1;
                if (resid) {
                    const float2 rv = *(const float2*)(resid + (size_t)rb2 * CCH + c);
                    v0 += rv.x; v1 += rv.y;
                }
                *(float2*)(out + (size_t)rb2 * CCH + c) = make_float2(v0, v1);
            }
        }
    }
}

// ---------------------------------------------------------------------
extern "C" void kernel_launch(void* const* d_in, const int* in_sizes, int n_in,
                              void* d_out, int out_size)
{
    const float* feats = (const float*)d_in[0];
    const float* emb   = (const float*)d_in[1];
    const int*   jidx  = (const int*)  d_in[2];
    const int*   nbr   = (const int*)  d_in[3];
    const float* gn1w  = (const float*)d_in[4];
    const float* gn1b  = (const float*)d_in[5];
    const float* w1    = (const float*)d_in[6];
    const float* b1    = (const float*)d_in[7];
    const float* embw  = (const float*)d_in[8];
    const float* embb  = (const float*)d_in[9];
    const float* gn2w  = (const float*)d_in[10];
    const float* gn2b  = (const float*)d_in[11];
    const float* w2    = (const float*)d_in[12];
    const float* b2    = (const float*)d_in[13];
    float* out = (float*)d_out;

    unsigned char *xp = nullptr, *w1p = nullptr, *w2p = nullptr;
    cudaGetSymbolAddress((void**)&xp,  g_xp);
    cudaGetSymbolAddress((void**)&w1p, g_w1p);
    cudaGetSymbolAddress((void**)&w2p, g_w2p);

    const int SMEM_CONV = 1024 + 2 * STAGE;   // align slack + 96KB
    cudaFuncSetAttribute(convmma_kernel,
                         cudaFuncAttributeMaxDynamicSharedMemorySize, SMEM_CONV);

    const int nblk_norm  = (NROWS * (CCH / 4) + 255) / 256;
    const int nblk_stats = (NROWS + 511) / 512;

    // weight packing (cheap; every replay for determinism)
    wpack_kernel<<<KTAP * CCH, 256>>>(w1, w1p);
    wpack_kernel<<<KTAP * CCH, 256>>>(w2, w2p);

    // --- GN1 -> packed ---
    reset_kernel<<<4, 256>>>(1);
    count_kernel<<<64, 256>>>(jidx, NROWS);
    stats_kernel<<<nblk_stats, 256>>>(feats, jidx, NROWS);
    finalize_kernel<<<1, 128>>>();
    norm_pack_kernel<<<nblk_norm, 256>>>(feats, jidx, gn1w, gn1b, xp, 0);

    // --- emb MLP ---
    emb_kernel<<<BGR, 512>>>(emb, embw, embb);

    // --- conv1: packed acts -> d_out (fp32 staging) ---
    convmma_kernel<<<NBLK_CONV, 512, SMEM_CONV>>>(xp, nbr, w1p, b1, nullptr, out, NROWS);

    // --- GN2 + FiLM -> packed ---
    reset_kernel<<<4, 256>>>(0);
    stats_kernel<<<nblk_stats, 256>>>(out, jidx, NROWS);
    finalize_kernel<<<1, 128>>>();
    norm_pack_kernel<<<nblk_norm, 256>>>(out, jidx, gn2w, gn2b, xp, 1);

    // --- conv2 + residual -> d_out ---
    convmma_kernel<<<NBLK_CONV, 512, SMEM_CONV>>>(xp, nbr, w2p, b2, feats, out, NROWS);
}

// round 4
// speedup vs baseline: 5.8661x; 1.0525x over previous
#include <cuda_runtime.h>
#include <cuda_bf16.h>
#include <cstdint>
#include <math.h>

// Problem constants (fixed by the dataset)
#define NROWS 200000
#define CCH   256
#define BGR   4
#define GRP   32
#define KTAP  27
#define CEMB  1024
#define EPSV  1e-5f

#define TILE_M    128
#define CHUNKS    8                    // 32-cin chunks per tap
#define NITER     (KTAP * CHUNKS)      // 216
#define NBLK_CONV ((NROWS + TILE_M - 1) / TILE_M)   // 1563

// packed row: 8 chunks x [32 hi bf16 (64B) | 32 lo bf16 (64B)] = 1024 B/row
#define ROWB   1024
#define ASTAGE 16384                   // 128 rows * 128B
#define BSTAGE 32768                   // 256 couts * 128B
#define STAGE  (ASTAGE + BSTAGE)       // 48KB per stage
#define NSTAGE 3

// -------- scratch (static __device__ — no runtime allocation) --------
__device__ unsigned char g_xp[(size_t)NROWS * ROWB];        // 204.8 MB packed acts
__device__ unsigned char g_w1p[(size_t)KTAP * CCH * 1024];  // 6.9 MB packed weights
__device__ unsigned char g_w2p[(size_t)KTAP * CCH * 1024];
__device__ float g_sum[BGR * CCH];
__device__ float g_sq[BGR * CCH];
__device__ float g_mean[BGR * GRP];
__device__ float g_rstd[BGR * GRP];
__device__ int   g_cnt[BGR];
__device__ float g_ss[BGR * 2 * CCH];

// ---------------------------------------------------------------------
__device__ __forceinline__ float silu_f(float v) { return v / (1.0f + expf(-v)); }

__device__ __forceinline__ uint32_t s2u(const void* p) {
    return (uint32_t)__cvta_generic_to_shared(p);
}
__device__ __forceinline__ void cp16(uint32_t dst, const void* src) {
    asm volatile("cp.async.cg.shared.global [%0], [%1], 16;" :: "r"(dst), "l"(src));
}
__device__ __forceinline__ void sts16_zero(uint32_t dst) {
    asm volatile("st.shared.v4.b32 [%0], {%1,%1,%1,%1};" :: "r"(dst), "r"(0u) : "memory");
}
__device__ __forceinline__ void ldsm4(uint32_t* r, uint32_t a) {
    asm volatile("ldmatrix.sync.aligned.m8n8.x4.shared.b16 {%0,%1,%2,%3}, [%4];"
                 : "=r"(r[0]), "=r"(r[1]), "=r"(r[2]), "=r"(r[3]) : "r"(a));
}
__device__ __forceinline__ void mma_bf16(float* d, const uint32_t* a,
                                         uint32_t b0, uint32_t b1) {
    asm volatile(
        "mma.sync.aligned.m16n8k16.row.col.f32.bf16.bf16.f32 "
        "{%0,%1,%2,%3}, {%4,%5,%6,%7}, {%8,%9}, {%0,%1,%2,%3};"
        : "+f"(d[0]), "+f"(d[1]), "+f"(d[2]), "+f"(d[3])
        : "r"(a[0]), "r"(a[1]), "r"(a[2]), "r"(a[3]), "r"(b0), "r"(b1));
}

__device__ __forceinline__ void split_bf16(float v, __nv_bfloat16& h, __nv_bfloat16& l) {
    h = __float2bfloat16(v);
    l = __float2bfloat16(v - __bfloat162float(h));
}
__device__ __forceinline__ uint32_t pack2(__nv_bfloat16 a, __nv_bfloat16 b) {
    __nv_bfloat162 p = __halves2bfloat162(a, b);
    return *reinterpret_cast<uint32_t*>(&p);
}

// -------- reset accumulators (graph replay safe) --------
__global__ void reset_kernel(int zero_cnt) {
    int t = blockIdx.x * blockDim.x + threadIdx.x;
    if (t < BGR * CCH) { g_sum[t] = 0.0f; g_sq[t] = 0.0f; }
    if (zero_cnt && t < BGR) g_cnt[t] = 0;
}

__global__ void count_kernel(const int* __restrict__ jidx, int n) {
    int c0 = 0, c1 = 0, c2 = 0, c3 = 0;
    for (int i = blockIdx.x * blockDim.x + threadIdx.x; i < n;
         i += gridDim.x * blockDim.x) {
        int b = jidx[i];
        c0 += (b == 0); c1 += (b == 1); c2 += (b == 2); c3 += (b == 3);
    }
    if (c0) atomicAdd(&g_cnt[0], c0);
    if (c1) atomicAdd(&g_cnt[1], c1);
    if (c2) atomicAdd(&g_cnt[2], c2);
    if (c3) atomicAdd(&g_cnt[3], c3);
}

__global__ void stats_kernel(const float* __restrict__ x,
                             const int* __restrict__ jidx, int nrows) {
    const int t = threadIdx.x;                 // channel, blockDim = 256
    int r0 = blockIdx.x * 512;
    int r1 = r0 + 512; if (r1 > nrows) r1 = nrows;
    float s = 0.0f, sq = 0.0f; int cur = -1;
    for (int r = r0; r < r1; ++r) {
        int b = jidx[r];
        if (b != cur) {
            if (cur >= 0) {
                atomicAdd(&g_sum[cur * CCH + t], s);
                atomicAdd(&g_sq[cur * CCH + t], sq);
            }
            cur = b; s = 0.0f; sq = 0.0f;
        }
        float v = x[(size_t)r * CCH + t];
        s += v; sq += v * v;
    }
    if (cur >= 0) {
        atomicAdd(&g_sum[cur * CCH + t], s);
        atomicAdd(&g_sq[cur * CCH + t], sq);
    }
}

__global__ void finalize_kernel() {
    int t = threadIdx.x;
    if (t < BGR * GRP) {
        int b = t / GRP, g = t % GRP;
        float s = 0.0f, sq = 0.0f;
        #pragma unroll
        for (int j = 0; j < 8; ++j) {
            s  += g_sum[b * CCH + g * 8 + j];
            sq += g_sq [b * CCH + g * 8 + j];
        }
        float denom = (float)g_cnt[b] * 8.0f;
        float mean = s / denom;
        float var  = sq / denom - mean * mean;
        g_mean[t] = mean;
        g_rstd[t] = rsqrtf(var + EPSV);
    }
}

// -------- GN + SiLU -> packed bf16 hi/lo rows (film=0: GN1; film=1: GN2+FiLM) --
__global__ void norm_pack_kernel(const float* __restrict__ x,
                                 const int* __restrict__ jidx,
                                 const float* __restrict__ w,
                                 const float* __restrict__ bb,
                                 unsigned char* __restrict__ xp, int film) {
    size_t i4 = (size_t)blockIdx.x * blockDim.x + threadIdx.x;
    if (i4 >= (size_t)NROWS * (CCH / 4)) return;
    int n = (int)(i4 >> 6);
    int c = ((int)i4 & 63) * 4;
    int b = jidx[n];
    int g = c >> 3;
    float mean = g_mean[b * GRP + g];
    float rstd = g_rstd[b * GRP + g];
    float4 xv = *(const float4*)(x + i4 * 4);
    float4 wv = *(const float4*)(w + c);
    float4 bv = *(const float4*)(bb + c);
    float o[4];
    o[0] = (xv.x - mean) * rstd * wv.x + bv.x;
    o[1] = (xv.y - mean) * rstd * wv.y + bv.y;
    o[2] = (xv.z - mean) * rstd * wv.z + bv.z;
    o[3] = (xv.w - mean) * rstd * wv.w + bv.w;
    if (film) {
        float4 sc = *(const float4*)(g_ss + b * (2 * CCH) + c);
        float4 sh = *(const float4*)(g_ss + b * (2 * CCH) + CCH + c);
        o[0] = o[0] * (1.0f + sc.x) + sh.x;
        o[1] = o[1] * (1.0f + sc.y) + sh.y;
        o[2] = o[2] * (1.0f + sc.z) + sh.z;
        o[3] = o[3] * (1.0f + sc.w) + sh.w;
    }
    __nv_bfloat16 h[4], l[4];
    #pragma unroll
    for (int j = 0; j < 4; ++j) {
        float s = silu_f(o[j]);
        split_bf16(s, h[j], l[j]);
    }
    size_t base = (size_t)n * ROWB + (size_t)(c >> 5) * 128 + (size_t)(c & 31) * 2;
    uint2 hv = make_uint2(pack2(h[0], h[1]), pack2(h[2], h[3]));
    uint2 lv = make_uint2(pack2(l[0], l[1]), pack2(l[2], l[3]));
    *(uint2*)(xp + base)      = hv;
    *(uint2*)(xp + base + 64) = lv;
}

// -------- pack W[k][cin][cout] -> wp[(k*256+cout)*8 + cin/32][32hi|32lo] ------
__global__ void wpack_kernel(const float* __restrict__ W,
                             unsigned char* __restrict__ wp) {
    int bid = blockIdx.x;               // 0 .. 27*256-1
    int k = bid >> 8, cout = bid & 255;
    int cin = threadIdx.x;              // 0..255
    float v = W[((size_t)(k * CCH + cin)) * CCH + cout];
    __nv_bfloat16 h, l;
    split_bf16(v, h, l);
    size_t base = ((size_t)(k * CCH + cout) * 8 + (cin >> 5)) * 128 + (size_t)(cin & 31) * 2;
    *(__nv_bfloat16*)(wp + base)      = h;
    *(__nv_bfloat16*)(wp + base + 64) = l;
}

// -------- embedding MLP --------
__global__ void emb_kernel(const float* __restrict__ emb,
                           const float* __restrict__ ew,
                           const float* __restrict__ eb) {
    __shared__ float se[CEMB];
    int b = blockIdx.x;
    int t = threadIdx.x;                // blockDim = 512
    for (int i = t; i < CEMB; i += 512) se[i] = silu_f(emb[b * CEMB + i]);
    __syncthreads();
    float acc = eb[t];
    for (int i = 0; i < CEMB; ++i)
        acc += se[i] * ew[i * (2 * CCH) + t];
    g_ss[b * (2 * CCH) + t] = acc;
}

// ================= HMMA sparse-conv GEMM =================
// CTA: 512 thr, tile 128 rows x 256 cout. Warp grid 4m x 4n, warp tile 32x64.
// fp32 emulated as Ah*Bh + Ah*Bl + Al*Bh on bf16 mma.sync (3 passes).
// 3-stage cp.async pipeline, ONE __syncthreads per iteration:
//   wait_group -> sync -> issue loads(it+2) -> compute(it)
// The sync both publishes stage it and protects stage (it+2)'s buffer
// (its previous reader, compute(it-1), precedes the sync in program order).
__global__ void __launch_bounds__(512, 1) convmma_kernel(
    const unsigned char* __restrict__ xp, const int* __restrict__ nbr,
    const unsigned char* __restrict__ wp, const float* __restrict__ bias,
    const float* __restrict__ resid, float* __restrict__ out, int nrows)
{
    extern __shared__ unsigned char dsm[];
    const int tid  = threadIdx.x;
    const int lane = tid & 31;
    const int wid  = tid >> 5;
    const int wm   = wid & 3;            // warp m-tile (32 rows each)
    const int wn   = wid >> 2;           // warp n-tile (64 couts each)
    const int row0 = blockIdx.x * TILE_M;

    uint32_t sb = (s2u(dsm) + 1023u) & ~1023u;   // 1KB-aligned

    // ldmatrix lane decomposition
    const int l7 = lane & 7;
    const int lq = (lane >> 3) & 1;
    const int lh = (lane >> 4) & 1;

    // gather mapping: A rows (thread t -> row t>>2, 2 segs), B couts (t>>1, 4 segs)
    const int grow  = tid >> 2;
    const bool gok  = (row0 + grow) < nrows;
    const int aseg0 = (tid & 3) * 2;
    const int bco   = tid >> 1;
    const int bseg0 = (tid & 1) * 4;

    float acc[2][8][4];
#pragma unroll
    for (int mt = 0; mt < 2; ++mt)
#pragma unroll
        for (int nt = 0; nt < 8; ++nt)
#pragma unroll
            for (int q = 0; q < 4; ++q) acc[mt][nt][q] = 0.0f;

    int gidx = -1;
    int lbuf = 0;                        // stage index for next load (wraps mod 3)
    auto load_chunk = [&](int j) {
        const int kk = j >> 3, cc = j & 7;
        if (cc == 0) gidx = gok ? nbr[(size_t)(row0 + grow) * KTAP + kk] : -1;
        const uint32_t ab = sb + lbuf * STAGE + (uint32_t)grow * 128u;
        if (gidx >= 0) {
            const unsigned char* src = xp + (size_t)gidx * ROWB + (size_t)cc * 128;
#pragma unroll
            for (int u = 0; u < 2; ++u) {
                int seg = aseg0 + u;
                cp16(ab + (uint32_t)((seg ^ (grow & 7)) * 16), src + seg * 16);
            }
        } else {
#pragma unroll
            for (int u = 0; u < 2; ++u) {
                int seg = aseg0 + u;
                sts16_zero(ab + (uint32_t)((seg ^ (grow & 7)) * 16));
            }
        }
        const unsigned char* bsrc = wp + ((size_t)(kk * CCH + bco) * 8 + cc) * 128;
        const uint32_t bb = sb + lbuf * STAGE + ASTAGE + (uint32_t)bco * 128u;
#pragma unroll
        for (int u = 0; u < 4; ++u) {
            int seg = bseg0 + u;
            cp16(bb + (uint32_t)((seg ^ (bco & 7)) * 16), bsrc + seg * 16);
        }
        asm volatile("cp.async.commit_group;");
        if (++lbuf == NSTAGE) lbuf = 0;
    };

    // prologue: stages 0 and 1 in flight
    load_chunk(0);
    load_chunk(1);

    int cbuf = 0;                        // stage index for compute (wraps mod 3)
    for (int it = 0; it < NITER; ++it) {
        // stage `it` ready (own copies), then publish + protect via one barrier
        if (it + 1 < NITER) asm volatile("cp.async.wait_group 1;");
        else                asm volatile("cp.async.wait_group 0;");
        __syncthreads();

        if (it + 2 < NITER) load_chunk(it + 2);   // lands during next 2 computes

        const uint32_t ab = sb + cbuf * STAGE;
        const uint32_t bb = ab + ASTAGE;
        if (++cbuf == NSTAGE) cbuf = 0;

#pragma unroll
        for (int ks = 0; ks < 2; ++ks) {
            // A fragments (hi and lo) for both m-tiles
            uint32_t ah[2][4], al[2][4];
#pragma unroll
            for (int mt = 0; mt < 2; ++mt) {
                const int m_r  = wm * 32 + mt * 16 + l7 + lq * 8;
                const int sg_h = ks * 2 + lh;
                const uint32_t rbase = ab + (uint32_t)m_r * 128u;
                ldsm4(ah[mt], rbase + (uint32_t)(((sg_h    ) ^ l7) * 16));
                ldsm4(al[mt], rbase + (uint32_t)(((sg_h + 4) ^ l7) * 16));
            }
#pragma unroll
            for (int p = 0; p < 4; ++p) {         // pairs of n-tiles
                const int n_r  = wn * 64 + p * 16 + lh * 8 + l7;
                const int sg_h = ks * 2 + lq;
                const uint32_t rbase = bb + (uint32_t)n_r * 128u;
                uint32_t bh[4], bl[4];
                ldsm4(bh, rbase + (uint32_t)(((sg_h    ) ^ l7) * 16));
                ldsm4(bl, rbase + (uint32_t)(((sg_h + 4) ^ l7) * 16));
#pragma unroll
                for (int mt = 0; mt < 2; ++mt)
#pragma unroll
                    for (int q = 0; q < 2; ++q) {
                        float* d = acc[mt][p * 2 + q];
                        mma_bf16(d, ah[mt], bh[2 * q], bh[2 * q + 1]);  // Ah*Bh
                        mma_bf16(d, ah[mt], bl[2 * q], bl[2 * q + 1]);  // Ah*Bl
                        mma_bf16(d, al[mt], bh[2 * q], bh[2 * q + 1]);  // Al*Bh
                    }
            }
        }
    }

    // ---- epilogue ----
    const int tq = lane >> 2;             // 0..7
    const int tr = lane & 3;              // 0..3
#pragma unroll
    for (int mt = 0; mt < 2; ++mt) {
        const int ra = row0 + wm * 32 + mt * 16 + tq;
        const int rb2 = ra + 8;
#pragma unroll
        for (int nt = 0; nt < 8; ++nt) {
            const int c = wn * 64 + nt * 8 + tr * 2;
            const float b0 = bias[c], b1 = bias[c + 1];
            if (ra < nrows) {
                float v0 = acc[mt][nt][0] + b0;
                float v1 = acc[mt][nt][1] + b1;
                if (resid) {
                    const float2 rv = *(const float2*)(resid + (size_t)ra * CCH + c);
                    v0 += rv.x; v1 += rv.y;
                }
                *(float2*)(out + (size_t)ra * CCH + c) = make_float2(v0, v1);
            }
            if (rb2 < nrows) {
                float v0 = acc[mt][nt][2] + b0;
                float v1 = acc[mt][nt][3] + b1;
                if (resid) {
                    const float2 rv = *(const float2*)(resid + (size_t)rb2 * CCH + c);
                    v0 += rv.x; v1 += rv.y;
                }
                *(float2*)(out + (size_t)rb2 * CCH + c) = make_float2(v0, v1);
            }
        }
    }
}

// ---------------------------------------------------------------------
extern "C" void kernel_launch(void* const* d_in, const int* in_sizes, int n_in,
                              void* d_out, int out_size)
{
    const float* feats = (const float*)d_in[0];
    const float* emb   = (const float*)d_in[1];
    const int*   jidx  = (const int*)  d_in[2];
    const int*   nbr   = (const int*)  d_in[3];
    const float* gn1w  = (const float*)d_in[4];
    const float* gn1b  = (const float*)d_in[5];
    const float* w1    = (const float*)d_in[6];
    const float* b1    = (const float*)d_in[7];
    const float* embw  = (const float*)d_in[8];
    const float* embb  = (const float*)d_in[9];
    const float* gn2w  = (const float*)d_in[10];
    const float* gn2b  = (const float*)d_in[11];
    const float* w2    = (const float*)d_in[12];
    const float* b2    = (const float*)d_in[13];
    float* out = (float*)d_out;

    unsigned char *xp = nullptr, *w1p = nullptr, *w2p = nullptr;
    cudaGetSymbolAddress((void**)&xp,  g_xp);
    cudaGetSymbolAddress((void**)&w1p, g_w1p);
    cudaGetSymbolAddress((void**)&w2p, g_w2p);

    const int SMEM_CONV = 1024 + NSTAGE * STAGE;   // align slack + 144KB
    cudaFuncSetAttribute(convmma_kernel,
                         cudaFuncAttributeMaxDynamicSharedMemorySize, SMEM_CONV);

    const int nblk_norm  = (NROWS * (CCH / 4) + 255) / 256;
    const int nblk_stats = (NROWS + 511) / 512;

    // weight packing (cheap; every replay for determinism)
    wpack_kernel<<<KTAP * CCH, 256>>>(w1, w1p);
    wpack_kernel<<<KTAP * CCH, 256>>>(w2, w2p);

    // --- GN1 -> packed ---
    reset_kernel<<<4, 256>>>(1);
    count_kernel<<<64, 256>>>(jidx, NROWS);
    stats_kernel<<<nblk_stats, 256>>>(feats, jidx, NROWS);
    finalize_kernel<<<1, 128>>>();
    norm_pack_kernel<<<nblk_norm, 256>>>(feats, jidx, gn1w, gn1b, xp, 0);

    // --- emb MLP ---
    emb_kernel<<<BGR, 512>>>(emb, embw, embb);

    // --- conv1: packed acts -> d_out (fp32 staging) ---
    convmma_kernel<<<NBLK_CONV, 512, SMEM_CONV>>>(xp, nbr, w1p, b1, nullptr, out, NROWS);

    // --- GN2 + FiLM -> packed ---
    reset_kernel<<<4, 256>>>(0);
    stats_kernel<<<nblk_stats, 256>>>(out, jidx, NROWS);
    finalize_kernel<<<1, 128>>>();
    norm_pack_kernel<<<nblk_norm, 256>>>(out, jidx, gn2w, gn2b, xp, 1);

    // --- conv2 + residual -> d_out ---
    convmma_kernel<<<NBLK_CONV, 512, SMEM_CONV>>>(xp, nbr, w2p, b2, feats, out, NROWS);
}